// round 1
// baseline (speedup 1.0000x reference)
#include <cuda_runtime.h>

#define B_    8
#define NV_   128
#define NQ_   512
#define DIN   128
#define DPROJ 512
#define HD    256

// ---- scratch (no allocations allowed) ----
__device__ float g_v[B_*NV_*DPROJ];    // v_ : [b][i][h*256+d]
__device__ float g_q[B_*NQ_*DPROJ];    // q_ : [b][j][h*256+d]
__device__ float g_head[B_*DPROJ];     // head : [b][h*256+d]

// ============================================================
// Generic tiled SGEMM + bias: C[M,N] = A[M,K] @ B[K,N] + bias
// 64x64 tile, k-tile 16, 256 threads, 4x4 micro-tile, float4 smem reads.
// Requires M,N mult of 64, K mult of 16, all pointers 16B aligned.
// ============================================================
__global__ __launch_bounds__(256) void gemm_bias_k(
    const float* __restrict__ A, const float* __restrict__ Bm,
    const float* __restrict__ bias, float* __restrict__ C,
    int M, int N, int K)
{
    __shared__ __align__(16) float As[16*64];  // [kk][r]
    __shared__ __align__(16) float Bs[16*64];  // [kk][c]
    int tid = threadIdx.x;
    int tx = tid & 15, ty = tid >> 4;
    int bm = blockIdx.y * 64, bn = blockIdx.x * 64;

    float acc[4][4] = {};
    for (int k0 = 0; k0 < K; k0 += 16) {
        // load A tile (transposed into k-major)
        {
            int r = tid & 63, kq = tid >> 6;  // kq 0..3 -> kk = kq*4..+3
            float4 a4 = *(const float4*)(A + (size_t)(bm + r)*K + k0 + kq*4);
            As[(kq*4+0)*64 + r] = a4.x;
            As[(kq*4+1)*64 + r] = a4.y;
            As[(kq*4+2)*64 + r] = a4.z;
            As[(kq*4+3)*64 + r] = a4.w;
        }
        // load B tile (already k-major)
        {
            int c = (tid & 15)*4, kk = tid >> 4;
            *(float4*)(Bs + kk*64 + c) =
                *(const float4*)(Bm + (size_t)(k0+kk)*N + bn + c);
        }
        __syncthreads();
        #pragma unroll
        for (int k = 0; k < 16; k++) {
            float4 a = *(float4*)(As + k*64 + ty*4);
            float4 b = *(float4*)(Bs + k*64 + tx*4);
            float av[4] = {a.x, a.y, a.z, a.w};
            float bv[4] = {b.x, b.y, b.z, b.w};
            #pragma unroll
            for (int r = 0; r < 4; r++)
                #pragma unroll
                for (int c = 0; c < 4; c++)
                    acc[r][c] += av[r]*bv[c];
        }
        __syncthreads();
    }
    float4 b4 = *(const float4*)(bias + bn + tx*4);
    float bb[4] = {b4.x, b4.y, b4.z, b4.w};
    #pragma unroll
    for (int r = 0; r < 4; r++) {
        float4 o;
        o.x = acc[r][0] + bb[0];
        o.y = acc[r][1] + bb[1];
        o.z = acc[r][2] + bb[2];
        o.w = acc[r][3] + bb[3];
        *(float4*)(C + (size_t)(bm + ty*4 + r)*N + bn + tx*4) = o;
    }
}

// ============================================================
// zero head accumulator
// ============================================================
__global__ void zero_head_k()
{
    int i = blockIdx.x*256 + threadIdx.x;
    if (i < B_*DPROJ) g_head[i] = 0.f;
}

// ============================================================
// Fused score + softmax(over i) + att write + s = att^T v + head atomics.
// One CTA per (b, h, j-tile of 64). 256 threads.
//   score[i,j] = sum_d (v_[i,d]*wa[d]) * q_[j,d]     (ba drops out of softmax)
//   att[:,j]   = softmax_i(score[:,j])
//   head[d]   += sum_j q_[j,d] * sum_i att[i,j]*v_[i,d]
// ============================================================
__global__ __launch_bounds__(256) void score_kernel(
    const float* __restrict__ wa, float* __restrict__ att_out)
{
    extern __shared__ __align__(16) float sm[];
    float* sc  = sm;                // 128*65 (padded) - exp(score) after softmax
    float* As  = sm + 128*65;       // 4096 : phase1 k-major vw tile / phase2 i-major v chunk
    float* Bs  = As + 4096;         // 2048 : phase1 k-major q tile
    float* inv = Bs + 2048;         // 64   : 1/colsum

    int tid = threadIdx.x;
    int jt = blockIdx.x;            // 0..7 (j tile of 64)
    int h  = blockIdx.y;            // 0..1
    int b  = blockIdx.z;            // 0..7

    const float* vptr = g_v + (size_t)b*NV_*DPROJ + h*HD;              // row stride 512
    const float* qptr = g_q + (size_t)b*NQ_*DPROJ + (size_t)(jt*64)*DPROJ + h*HD;

    // ---------- phase 1: score GEMM 128(i) x 64(j), K=256 in chunks of 32 ----------
    int tx = tid & 15, ty = tid >> 4;   // tx->j (4 each), ty->i (8 each)
    float acc[8][4] = {};
    for (int d0 = 0; d0 < HD; d0 += 32) {
        #pragma unroll
        for (int l = 0; l < 4; l++) {
            int fi = tid*4 + l;
            int i = fi >> 3, kq = fi & 7;
            float4 v4 = *(const float4*)(vptr + (size_t)i*DPROJ + d0 + kq*4);
            float4 w4 = *(const float4*)(wa + d0 + kq*4);
            As[(kq*4+0)*128 + i] = v4.x*w4.x;
            As[(kq*4+1)*128 + i] = v4.y*w4.y;
            As[(kq*4+2)*128 + i] = v4.z*w4.z;
            As[(kq*4+3)*128 + i] = v4.w*w4.w;
        }
        #pragma unroll
        for (int l = 0; l < 2; l++) {
            int fi = tid*2 + l;
            int j = fi >> 3, kq = fi & 7;
            float4 q4 = *(const float4*)(qptr + (size_t)j*DPROJ + d0 + kq*4);
            Bs[(kq*4+0)*64 + j] = q4.x;
            Bs[(kq*4+1)*64 + j] = q4.y;
            Bs[(kq*4+2)*64 + j] = q4.z;
            Bs[(kq*4+3)*64 + j] = q4.w;
        }
        __syncthreads();
        #pragma unroll
        for (int k = 0; k < 32; k++) {
            float4 a0 = *(float4*)(As + k*128 + ty*8);
            float4 a1 = *(float4*)(As + k*128 + ty*8 + 4);
            float4 bq = *(float4*)(Bs + k*64 + tx*4);
            float av[8] = {a0.x,a0.y,a0.z,a0.w,a1.x,a1.y,a1.z,a1.w};
            float bv[4] = {bq.x,bq.y,bq.z,bq.w};
            #pragma unroll
            for (int r = 0; r < 8; r++)
                #pragma unroll
                for (int c = 0; c < 4; c++)
                    acc[r][c] += av[r]*bv[c];
        }
        __syncthreads();
    }
    #pragma unroll
    for (int r = 0; r < 8; r++)
        #pragma unroll
        for (int c = 0; c < 4; c++)
            sc[(ty*8 + r)*65 + tx*4 + c] = acc[r][c];
    __syncthreads();

    // ---------- softmax over i (128 rows), per column. 8 warps x 8 cols ----------
    int warp = tid >> 5, lane = tid & 31;
    #pragma unroll
    for (int jj = 0; jj < 8; jj++) {
        int j = warp*8 + jj;
        float x0 = sc[lane*65        + j];
        float x1 = sc[(lane+32)*65   + j];
        float x2 = sc[(lane+64)*65   + j];
        float x3 = sc[(lane+96)*65   + j];
        float m = fmaxf(fmaxf(x0,x1), fmaxf(x2,x3));
        #pragma unroll
        for (int off = 16; off; off >>= 1)
            m = fmaxf(m, __shfl_xor_sync(0xffffffffu, m, off));
        float e0 = __expf(x0-m), e1 = __expf(x1-m);
        float e2 = __expf(x2-m), e3 = __expf(x3-m);
        float s = e0+e1+e2+e3;
        #pragma unroll
        for (int off = 16; off; off >>= 1)
            s += __shfl_xor_sync(0xffffffffu, s, off);
        sc[lane*65      + j] = e0;
        sc[(lane+32)*65 + j] = e1;
        sc[(lane+64)*65 + j] = e2;
        sc[(lane+96)*65 + j] = e3;
        if (lane == 0) inv[j] = 1.0f / s;
    }
    __syncthreads();

    // ---------- write att (coalesced, row-major) ----------
    float* attp = att_out + (size_t)((b*2 + h)*NV_)*NQ_ + jt*64;
    #pragma unroll
    for (int it = 0; it < 32; it++) {
        int e = it*256 + tid;
        int i = e >> 6, j = e & 63;
        attp[(size_t)i*NQ_ + j] = sc[i*65 + j] * inv[j];
    }

    // ---------- phase 2: s[j,d] = sum_i e[i,j]*v[i,d]; head[d] += q[j,d]*inv[j]*s ----------
    int tx2 = tid & 7, ty2 = tid >> 3;   // tx2->d (4 each of 32-chunk), ty2->j (2 each)
    int hb = (b*2 + h)*HD;
    for (int d0 = 0; d0 < HD; d0 += 32) {
        __syncthreads();   // protect As reuse vs previous chunk's readers
        #pragma unroll
        for (int l = 0; l < 4; l++) {
            int fi = tid*4 + l;
            int i = fi >> 3, kq = fi & 7;
            *(float4*)(As + i*32 + kq*4) =
                *(const float4*)(vptr + (size_t)i*DPROJ + d0 + kq*4);
        }
        __syncthreads();
        float s0[4] = {}, s1[4] = {};
        #pragma unroll 4
        for (int i = 0; i < 128; i++) {
            float a0 = sc[i*65 + ty2*2];
            float a1 = sc[i*65 + ty2*2 + 1];
            float4 v4 = *(float4*)(As + i*32 + tx2*4);
            s0[0]+=a0*v4.x; s0[1]+=a0*v4.y; s0[2]+=a0*v4.z; s0[3]+=a0*v4.w;
            s1[0]+=a1*v4.x; s1[1]+=a1*v4.y; s1[2]+=a1*v4.z; s1[3]+=a1*v4.w;
        }
        float i0 = inv[ty2*2], i1 = inv[ty2*2+1];
        float4 q0 = *(const float4*)(qptr + (size_t)(ty2*2  )*DPROJ + d0 + tx2*4);
        float4 q1 = *(const float4*)(qptr + (size_t)(ty2*2+1)*DPROJ + d0 + tx2*4);
        float p[4];
        p[0] = i0*s0[0]*q0.x + i1*s1[0]*q1.x;
        p[1] = i0*s0[1]*q0.y + i1*s1[1]*q1.y;
        p[2] = i0*s0[2]*q0.z + i1*s1[2]*q1.z;
        p[3] = i0*s0[3]*q0.w + i1*s1[3]*q1.w;
        #pragma unroll
        for (int c = 0; c < 4; c++) {
            p[c] += __shfl_xor_sync(0xffffffffu, p[c], 8);
            p[c] += __shfl_xor_sync(0xffffffffu, p[c], 16);
        }
        if (lane < 8) {
            #pragma unroll
            for (int c = 0; c < 4; c++)
                atomicAdd(&g_head[hb + d0 + tx2*4 + c], p[c]);
        }
    }
}

// ============================================================
// fused = head(8x512) @ Wo(512x256) + bo. grid (8 dtiles, 8 b), 256 thr.
// ============================================================
__global__ __launch_bounds__(256) void fused_k(
    const float* __restrict__ Wo, const float* __restrict__ bo,
    float* __restrict__ out)
{
    __shared__ float hs[512];
    __shared__ float part[8][32];
    int dt = blockIdx.x, b = blockIdx.y;
    int tid = threadIdx.x;
    hs[tid]       = g_head[b*DPROJ + tid];
    hs[tid + 256] = g_head[b*DPROJ + 256 + tid];
    __syncthreads();
    int kg = tid >> 5, dl = tid & 31;
    int dcol = dt*32 + dl;
    float acc = 0.f;
    #pragma unroll 8
    for (int k = kg*64; k < kg*64 + 64; k++)
        acc += hs[k] * Wo[(size_t)k*HD + dcol];
    part[kg][dl] = acc;
    __syncthreads();
    if (tid < 32) {
        float s = 0.f;
        #pragma unroll
        for (int g = 0; g < 8; g++) s += part[g][tid];
        out[b*HD + dt*32 + tid] = s + bo[dt*32 + tid];
    }
}

// ============================================================
extern "C" void kernel_launch(void* const* d_in, const int* in_sizes, int n_in,
                              void* d_out, int out_size)
{
    const float* v  = (const float*)d_in[0];
    const float* q  = (const float*)d_in[1];
    const float* Wv = (const float*)d_in[2];
    const float* bv = (const float*)d_in[3];
    const float* Wq = (const float*)d_in[4];
    const float* bq = (const float*)d_in[5];
    const float* wa = (const float*)d_in[6];
    // d_in[7] = ba : constant shift before softmax -> mathematically drops out
    const float* Wo = (const float*)d_in[8];
    const float* bo = (const float*)d_in[9];
    float* out = (float*)d_out;

    float *gv, *gq;
    cudaGetSymbolAddress((void**)&gv, g_v);
    cudaGetSymbolAddress((void**)&gq, g_q);

    const int SMEM = (128*65 + 4096 + 2048 + 64) * (int)sizeof(float);  // 58112 B
    cudaFuncSetAttribute(score_kernel,
                         cudaFuncAttributeMaxDynamicSharedMemorySize, SMEM);

    zero_head_k<<<16, 256>>>();
    gemm_bias_k<<<dim3(8, 16), 256>>>(v, Wv, bv, gv, B_*NV_, DPROJ, DIN);
    gemm_bias_k<<<dim3(8, 64), 256>>>(q, Wq, bq, gq, B_*NQ_, DPROJ, DIN);
    score_kernel<<<dim3(8, 2, 8), 256, SMEM>>>(wa, out + B_*HD);
    fused_k<<<dim3(8, 8), 256>>>(Wo, bo, out);
}

// round 2
// speedup vs baseline: 2.7660x; 2.7660x over previous
#include <cuda_runtime.h>
#include <cuda_fp16.h>
#include <stdint.h>

#define B_    8
#define NV_   128
#define NQ_   512
#define DIN   128
#define DPROJ 512
#define HD    256

// strides (element units) chosen for conflict-free fragment loads (4-bank row step)
#define PR_S  136   // proj smem tiles [x][136] f16
#define VW_S  264   // score vw/q tiles [x][264] f16 (K=256)
#define SC_S  132   // score matrix [j][132] fp32 (i=128)
#define EB_S  136   // exp bf tile [j][136] f16 (i=128)
#define VT_S  136   // vT tile [d][136] f16 (i=128)

// ---- device scratch (allocations forbidden) ----
__device__ __half g_q16 [B_*NQ_*DPROJ];   // q_  : [b*512+j][512]
__device__ __half g_vw16[B_*NV_*DPROJ];   // v_*wa : [b*128+i][512]
__device__ __half g_vT16[B_*DPROJ*NV_];   // v_^T : [b][512][128]
__device__ __half g_WvT [DPROJ*DIN];      // Wv^T f16 [512][128]
__device__ __half g_WqT [DPROJ*DIN];      // Wq^T f16 [512][128]
__device__ float  g_head[B_*DPROJ];

__device__ __forceinline__ void mma16816(float* c, const uint32_t* a, const uint32_t* b) {
    asm volatile(
        "mma.sync.aligned.m16n8k16.row.col.f32.f16.f16.f32 "
        "{%0,%1,%2,%3}, {%4,%5,%6,%7}, {%8,%9}, {%0,%1,%2,%3};\n"
        : "+f"(c[0]), "+f"(c[1]), "+f"(c[2]), "+f"(c[3])
        : "r"(a[0]), "r"(a[1]), "r"(a[2]), "r"(a[3]), "r"(b[0]), "r"(b[1]));
}

// ============================================================
// W transpose + f16 convert: W[128][512] fp32 -> WT[512][128] f16
// ============================================================
__global__ void transposeW_k(const float* __restrict__ Wv, const float* __restrict__ Wq)
{
    const float* W = blockIdx.y ? Wq : Wv;
    __half* WT = blockIdx.y ? g_WqT : g_WvT;
    int idx = blockIdx.x*256 + threadIdx.x;   // 0..65535
    float val = W[idx];
    int k = idx >> 9, n = idx & 511;
    WT[n*DIN + k] = __float2half(val);
}

__global__ void zero_head_k()
{
    int i = blockIdx.x*256 + threadIdx.x;
    if (i < B_*DPROJ) g_head[i] = 0.f;
}

// ============================================================
// Projection: C[M,512] = A[M,128] @ W + bias ; tensor-core f16 mma.
// Tile 128x128, 256 threads (warps 2x4, warp tile 64x32). K=128.
// IS_V: also emit vw16 = C*wa and vT (transposed, via smem).
// ============================================================
template<int IS_V>
__global__ __launch_bounds__(256) void proj_k(
    const float* __restrict__ A, const float* __restrict__ bias,
    const float* __restrict__ wa)
{
    extern __shared__ __align__(16) char smem[];
    __half* As = (__half*)smem;                 // [128][136]
    __half* Bs = (__half*)(smem + 128*PR_S*2);  // [128][136]

    int t = threadIdx.x;
    int bn = blockIdx.x*128, bm = blockIdx.y*128;

    // load A fp32 -> f16 smem
    #pragma unroll
    for (int it = 0; it < 16; it++) {
        int fi = t + it*256;                 // 4096 float4
        int m = fi >> 5, k = (fi & 31)*4;
        float4 f = *(const float4*)(A + (size_t)(bm+m)*DIN + k);
        __half2 h0 = __floats2half2_rn(f.x, f.y);
        __half2 h1 = __floats2half2_rn(f.z, f.w);
        uint2 u; u.x = *(uint32_t*)&h0; u.y = *(uint32_t*)&h1;
        *(uint2*)(As + m*PR_S + k) = u;
    }
    // load WT f16 smem [n][k]
    const __half* WT = IS_V ? g_WvT : g_WqT;
    #pragma unroll
    for (int it = 0; it < 8; it++) {
        int fi = t + it*256;                 // 2048 float4
        int n = fi >> 4, k = (fi & 15)*8;
        *(float4*)(Bs + n*PR_S + k) = *(const float4*)(WT + (size_t)(bn+n)*DIN + k);
    }
    __syncthreads();

    int lane = t & 31, wid = t >> 5;
    int warpM = wid >> 2, warpN = wid & 3;
    int lr = lane >> 2, lc = (lane & 3)*2;

    float acc[4][4][4] = {};
    #pragma unroll
    for (int ks = 0; ks < 8; ks++) {
        int k0 = ks*16;
        uint32_t a[4][4], b[4][2];
        #pragma unroll
        for (int mt = 0; mt < 4; mt++) {
            const __half* ab = As + (warpM*64 + mt*16 + lr)*PR_S + k0 + lc;
            a[mt][0] = *(const uint32_t*)ab;
            a[mt][1] = *(const uint32_t*)(ab + 8*PR_S);
            a[mt][2] = *(const uint32_t*)(ab + 8);
            a[mt][3] = *(const uint32_t*)(ab + 8*PR_S + 8);
        }
        #pragma unroll
        for (int nt = 0; nt < 4; nt++) {
            const __half* bb = Bs + (warpN*32 + nt*8 + lr)*PR_S + k0 + lc;
            b[nt][0] = *(const uint32_t*)bb;
            b[nt][1] = *(const uint32_t*)(bb + 8);
        }
        #pragma unroll
        for (int mt = 0; mt < 4; mt++)
            #pragma unroll
            for (int nt = 0; nt < 4; nt++)
                mma16816(acc[mt][nt], a[mt], b[nt]);
    }

    if (IS_V) __syncthreads();   // As will be reused as transpose buffer

    #pragma unroll
    for (int mt = 0; mt < 4; mt++) {
        int rowL = warpM*64 + mt*16 + lr;
        int row = bm + rowL;
        #pragma unroll
        for (int nt = 0; nt < 4; nt++) {
            int colL = warpN*32 + nt*8 + lc;
            int col = bn + colL;
            float b0 = bias[col], b1 = bias[col+1];
            float v00 = acc[mt][nt][0] + b0, v01 = acc[mt][nt][1] + b1;
            float v10 = acc[mt][nt][2] + b0, v11 = acc[mt][nt][3] + b1;
            if (!IS_V) {
                __half2 p0 = __floats2half2_rn(v00, v01);
                __half2 p1 = __floats2half2_rn(v10, v11);
                *(__half2*)(g_q16 + (size_t)row*DPROJ + col) = p0;
                *(__half2*)(g_q16 + (size_t)(row+8)*DPROJ + col) = p1;
            } else {
                float w0 = wa[col & 255], w1 = wa[(col+1) & 255];
                __half2 p0 = __floats2half2_rn(v00*w0, v01*w1);
                __half2 p1 = __floats2half2_rn(v10*w0, v11*w1);
                *(__half2*)(g_vw16 + (size_t)row*DPROJ + col) = p0;
                *(__half2*)(g_vw16 + (size_t)(row+8)*DPROJ + col) = p1;
                // stage transpose: tr[n][m] in As region
                __half* tr = As;
                tr[colL*PR_S + rowL]       = __float2half(v00);
                tr[(colL+1)*PR_S + rowL]   = __float2half(v01);
                tr[colL*PR_S + rowL+8]     = __float2half(v10);
                tr[(colL+1)*PR_S + rowL+8] = __float2half(v11);
            }
        }
    }

    if (IS_V) {
        __syncthreads();
        const __half* tr = As;
        int b = bm >> 7;   // M tile == one batch
        #pragma unroll
        for (int it = 0; it < 8; it++) {
            int fi = t + it*256;             // 2048 float4
            int n = fi >> 4, k = (fi & 15)*8;
            *(float4*)(g_vT16 + ((size_t)b*DPROJ + bn + n)*NV_ + k) =
                *(const float4*)(tr + n*PR_S + k);
        }
    }
}

// ============================================================
// Score kernel: per (jt, h, b). Tensor-core phases.
//  P1: S[128i,64j] = vw[i,:256] @ q[j,:256]^T   (mma)
//  softmax over i (per column j), att written fp32
//  P2: T[64j,256d] = e[j,i] @ vT[d,i]^T          (mma)
//  head[d] += sum_j inv[j]*T[j,d]*q[j,d]         (shfl-reduce + atomics)
// ============================================================
__global__ __launch_bounds__(256) void score_k(float* __restrict__ att_out)
{
    extern __shared__ __align__(16) char smem[];
    __half* vws = (__half*)smem;                  // P1: [128][264] ; P2: vT [256][136]
    __half* qs  = (__half*)(smem + 69632);        // [64][264]
    float*  sc  = (float*) (smem + 103424);       // [64][132]
    __half* ebf = (__half*)(smem + 137216);       // [64][136]
    float*  inv = (float*) (smem + 154624);       // [64]

    int t = threadIdx.x;
    int jt = blockIdx.x, h = blockIdx.y, b = blockIdx.z;
    int lane = t & 31, wid = t >> 5;
    int lr = lane >> 2, lc = (lane & 3)*2;

    const __half* vwg = g_vw16 + ((size_t)b*NV_)*DPROJ + h*HD;
    const __half* qg  = g_q16  + ((size_t)(b*NQ_ + jt*64))*DPROJ + h*HD;

    #pragma unroll
    for (int it = 0; it < 16; it++) {
        int fi = t + it*256;                 // 4096 float4 : vw 128x256
        int i = fi >> 5, k = (fi & 31)*8;
        *(float4*)(vws + i*VW_S + k) = *(const float4*)(vwg + (size_t)i*DPROJ + k);
    }
    #pragma unroll
    for (int it = 0; it < 8; it++) {
        int fi = t + it*256;                 // 2048 float4 : q 64x256
        int j = fi >> 5, k = (fi & 31)*8;
        *(float4*)(qs + j*VW_S + k) = *(const float4*)(qg + (size_t)j*DPROJ + k);
    }
    __syncthreads();

    // -------- phase 1 --------
    {
        int warpI = wid >> 1, warpJ = wid & 1;
        int iw = warpI*32, jw = warpJ*32;
        float acc[2][4][4] = {};
        #pragma unroll
        for (int ks = 0; ks < 16; ks++) {
            int k0 = ks*16;
            uint32_t a[2][4], bq[4][2];
            #pragma unroll
            for (int mi = 0; mi < 2; mi++) {
                const __half* ab = vws + (iw + mi*16 + lr)*VW_S + k0 + lc;
                a[mi][0] = *(const uint32_t*)ab;
                a[mi][1] = *(const uint32_t*)(ab + 8*VW_S);
                a[mi][2] = *(const uint32_t*)(ab + 8);
                a[mi][3] = *(const uint32_t*)(ab + 8*VW_S + 8);
            }
            #pragma unroll
            for (int nj = 0; nj < 4; nj++) {
                const __half* bb = qs + (jw + nj*8 + lr)*VW_S + k0 + lc;
                bq[nj][0] = *(const uint32_t*)bb;
                bq[nj][1] = *(const uint32_t*)(bb + 8);
            }
            #pragma unroll
            for (int mi = 0; mi < 2; mi++)
                #pragma unroll
                for (int nj = 0; nj < 4; nj++)
                    mma16816(acc[mi][nj], a[mi], bq[nj]);
        }
        // store S transposed -> sc[j][i]
        #pragma unroll
        for (int mi = 0; mi < 2; mi++) {
            int i0 = iw + mi*16 + lr;
            #pragma unroll
            for (int nj = 0; nj < 4; nj++) {
                int j0 = jw + nj*8 + lc;
                sc[j0*SC_S + i0]       = acc[mi][nj][0];
                sc[(j0+1)*SC_S + i0]   = acc[mi][nj][1];
                sc[j0*SC_S + i0+8]     = acc[mi][nj][2];
                sc[(j0+1)*SC_S + i0+8] = acc[mi][nj][3];
            }
        }
    }
    __syncthreads();

    // -------- softmax over i (row j of sc) --------
    #pragma unroll
    for (int rr = 0; rr < 8; rr++) {
        int j = wid*8 + rr;
        float4 x = *(float4*)(sc + j*SC_S + lane*4);
        float mx = fmaxf(fmaxf(x.x, x.y), fmaxf(x.z, x.w));
        #pragma unroll
        for (int off = 16; off; off >>= 1)
            mx = fmaxf(mx, __shfl_xor_sync(0xffffffffu, mx, off));
        float4 e;
        e.x = __expf(x.x - mx); e.y = __expf(x.y - mx);
        e.z = __expf(x.z - mx); e.w = __expf(x.w - mx);
        float s = e.x + e.y + e.z + e.w;
        #pragma unroll
        for (int off = 16; off; off >>= 1)
            s += __shfl_xor_sync(0xffffffffu, s, off);
        *(float4*)(sc + j*SC_S + lane*4) = e;
        __half2 p0 = __floats2half2_rn(e.x, e.y);
        __half2 p1 = __floats2half2_rn(e.z, e.w);
        *(__half2*)(ebf + j*EB_S + lane*4)     = p0;
        *(__half2*)(ebf + j*EB_S + lane*4 + 2) = p1;
        if (lane == 0) inv[j] = 1.0f / s;
    }
    __syncthreads();

    // -------- load vT (overwrites vws) + write att --------
    const __half* vtg = g_vT16 + ((size_t)b*DPROJ + h*HD)*NV_;
    #pragma unroll
    for (int it = 0; it < 16; it++) {
        int fi = t + it*256;                 // 4096 float4 : vT 256x128
        int d = fi >> 4, k = (fi & 15)*8;
        *(float4*)(vws + d*VT_S + k) = *(const float4*)(vtg + (size_t)d*NV_ + k);
    }
    float* attp = att_out + ((size_t)(b*2 + h)*NV_)*NQ_ + jt*64;
    #pragma unroll
    for (int it = 0; it < 32; it++) {
        int e = it*256 + t;
        int i = e >> 6, j = e & 63;
        attp[(size_t)i*NQ_ + j] = sc[j*SC_S + i] * inv[j];
    }
    __syncthreads();

    // -------- phase 2 --------
    {
        int warpJ2 = wid >> 2, warpD = wid & 3;
        int jw2 = warpJ2*32, dw = warpD*64;
        float acc[2][8][4] = {};
        #pragma unroll
        for (int ks = 0; ks < 8; ks++) {
            int k0 = ks*16;
            uint32_t a[2][4], bv[8][2];
            #pragma unroll
            for (int mi = 0; mi < 2; mi++) {
                const __half* ab = ebf + (jw2 + mi*16 + lr)*EB_S + k0 + lc;
                a[mi][0] = *(const uint32_t*)ab;
                a[mi][1] = *(const uint32_t*)(ab + 8*EB_S);
                a[mi][2] = *(const uint32_t*)(ab + 8);
                a[mi][3] = *(const uint32_t*)(ab + 8*EB_S + 8);
            }
            #pragma unroll
            for (int nt = 0; nt < 8; nt++) {
                const __half* bb = vws + (dw + nt*8 + lr)*VT_S + k0 + lc;
                bv[nt][0] = *(const uint32_t*)bb;
                bv[nt][1] = *(const uint32_t*)(bb + 8);
            }
            #pragma unroll
            for (int mi = 0; mi < 2; mi++)
                #pragma unroll
                for (int nt = 0; nt < 8; nt++)
                    mma16816(acc[mi][nt], a[mi], bv[nt]);
        }
        // weight by inv[j]*q[j,d], reduce over j, atomically add to head
        float* headp = g_head + (b*2 + h)*HD;
        #pragma unroll
        for (int mi = 0; mi < 2; mi++) {
            int j0 = jw2 + mi*16 + lr, j1 = j0 + 8;
            float w0 = inv[j0], w1 = inv[j1];
            #pragma unroll
            for (int nt = 0; nt < 8; nt++) {
                int d0 = dw + nt*8 + lc;
                float q00 = __half2float(qs[j0*VW_S + d0]);
                float q01 = __half2float(qs[j0*VW_S + d0+1]);
                float q10 = __half2float(qs[j1*VW_S + d0]);
                float q11 = __half2float(qs[j1*VW_S + d0+1]);
                float va = acc[mi][nt][0]*w0*q00 + acc[mi][nt][2]*w1*q10;
                float vb = acc[mi][nt][1]*w0*q01 + acc[mi][nt][3]*w1*q11;
                va += __shfl_xor_sync(0xffffffffu, va, 4);
                va += __shfl_xor_sync(0xffffffffu, va, 8);
                va += __shfl_xor_sync(0xffffffffu, va, 16);
                vb += __shfl_xor_sync(0xffffffffu, vb, 4);
                vb += __shfl_xor_sync(0xffffffffu, vb, 8);
                vb += __shfl_xor_sync(0xffffffffu, vb, 16);
                if (lr == 0) {
                    atomicAdd(headp + d0,     va);
                    atomicAdd(headp + d0 + 1, vb);
                }
            }
        }
    }
}

// ============================================================
// fused = head(8x512) @ Wo(512x256) + bo
// ============================================================
__global__ __launch_bounds__(256) void fused_k(
    const float* __restrict__ Wo, const float* __restrict__ bo,
    float* __restrict__ out)
{
    __shared__ float hs[512];
    __shared__ float part[8][32];
    int dt = blockIdx.x, b = blockIdx.y;
    int tid = threadIdx.x;
    hs[tid]       = g_head[b*DPROJ + tid];
    hs[tid + 256] = g_head[b*DPROJ + 256 + tid];
    __syncthreads();
    int kg = tid >> 5, dl = tid & 31;
    int dcol = dt*32 + dl;
    float acc = 0.f;
    #pragma unroll 8
    for (int k = kg*64; k < kg*64 + 64; k++)
        acc += hs[k] * Wo[(size_t)k*HD + dcol];
    part[kg][dl] = acc;
    __syncthreads();
    if (tid < 32) {
        float s = 0.f;
        #pragma unroll
        for (int g = 0; g < 8; g++) s += part[g][tid];
        out[b*HD + dt*32 + tid] = s + bo[dt*32 + tid];
    }
}

// ============================================================
extern "C" void kernel_launch(void* const* d_in, const int* in_sizes, int n_in,
                              void* d_out, int out_size)
{
    const float* v  = (const float*)d_in[0];
    const float* q  = (const float*)d_in[1];
    const float* Wv = (const float*)d_in[2];
    const float* bv = (const float*)d_in[3];
    const float* Wq = (const float*)d_in[4];
    const float* bq = (const float*)d_in[5];
    const float* wa = (const float*)d_in[6];
    // d_in[7] = ba : constant shift before softmax -> drops out
    const float* Wo = (const float*)d_in[8];
    const float* bo = (const float*)d_in[9];
    float* out = (float*)d_out;

    const int PSM = 2 * 128 * PR_S * 2;          // 69632 B
    const int SSM = 154880;                       // score smem
    cudaFuncSetAttribute(proj_k<0>, cudaFuncAttributeMaxDynamicSharedMemorySize, PSM);
    cudaFuncSetAttribute(proj_k<1>, cudaFuncAttributeMaxDynamicSharedMemorySize, PSM);
    cudaFuncSetAttribute(score_k,   cudaFuncAttributeMaxDynamicSharedMemorySize, SSM);

    transposeW_k<<<dim3(256, 2), 256>>>(Wv, Wq);
    zero_head_k<<<16, 256>>>();
    proj_k<1><<<dim3(4, 8),  256, PSM>>>(v, bv, wa);
    proj_k<0><<<dim3(4, 32), 256, PSM>>>(q, bq, wa);
    score_k<<<dim3(8, 2, 8), 256, SSM>>>(out + B_*HD);
    fused_k<<<dim3(8, 8), 256>>>(Wo, bo, out);
}